// round 1
// baseline (speedup 1.0000x reference)
#include <cuda_runtime.h>
#include <cstdint>

// Dense 2D spatial transformer (bilinear warp with zero-padded border).
// input1: [1,1,4096,4096] f32 image
// input2: [1,2,4096,4096] f32 flow (plane 0 = dH, plane 1 = dW)
// out:    [1,1,4096,4096] f32
//
// Reference semantics:
//   H_up = flow_h + h + 1 ; W_up = flow_w + w + 1   (into 4098x4098 zero-padded image)
//   hf = clip(floor(H_up), 0, 4097); hc = clip(hf+1, 0, 4097); same for w
//   dH = hc - H_up; dW = wc - W_up   (weights use CLIPPED hc/wc)
//   out = v(hf,wf)*dW*dH + v(hc,wf)*dW*(1-dH) + v(hf,wc)*(1-dW)*dH + v(hc,wc)*(1-dW)*(1-dH)

#define H_DIM 4096
#define W_DIM 4096
#define HP_MAX 4097   // padded dim 4098, max index 4097

__device__ __forceinline__ float fetch_padded(const float* __restrict__ img, int h, int w) {
    // virtual zero padding: padded (h,w) maps to img[(h-1)*W + (w-1)] when interior
    bool in = (h >= 1) & (h <= H_DIM) & (w >= 1) & (w <= W_DIM);
    return in ? __ldg(img + (size_t)(h - 1) * W_DIM + (w - 1)) : 0.0f;
}

__device__ __forceinline__ float warp_one(const float* __restrict__ img,
                                          float flow_h, float flow_w,
                                          int h, int w) {
    float Hu = flow_h + (float)h + 1.0f;
    float Wu = flow_w + (float)w + 1.0f;

    int hf = (int)floorf(Hu);
    int wf = (int)floorf(Wu);
    int hc = hf + 1;
    int wc = wf + 1;

    hf = min(max(hf, 0), HP_MAX);
    hc = min(max(hc, 0), HP_MAX);
    wf = min(max(wf, 0), HP_MAX);
    wc = min(max(wc, 0), HP_MAX);

    float dH = (float)hc - Hu;
    float dW = (float)wc - Wu;
    float eH = 1.0f - dH;
    float eW = 1.0f - dW;

    float v00 = fetch_padded(img, hf, wf);
    float v10 = fetch_padded(img, hc, wf);
    float v01 = fetch_padded(img, hf, wc);
    float v11 = fetch_padded(img, hc, wc);

    return v00 * (dW * dH) + v10 * (dW * eH) + v01 * (eW * dH) + v11 * (eW * eW == eW * eW ? eW * eH : eW * eH);
}

__global__ void __launch_bounds__(256)
dense_warp_kernel(const float* __restrict__ img,
                  const float* __restrict__ flowH,
                  const float* __restrict__ flowW,
                  float* __restrict__ out) {
    // each thread: 4 consecutive pixels (same row; W divisible by 4)
    int t = blockIdx.x * blockDim.x + threadIdx.x;
    size_t base = (size_t)t * 4;
    if (base >= (size_t)H_DIM * W_DIM) return;

    float4 fh = *reinterpret_cast<const float4*>(flowH + base);
    float4 fw = *reinterpret_cast<const float4*>(flowW + base);

    int h = (int)(base >> 12);          // / 4096
    int w = (int)(base & (W_DIM - 1));  // % 4096

    float4 o;
    o.x = warp_one(img, fh.x, fw.x, h, w + 0);
    o.y = warp_one(img, fh.y, fw.y, h, w + 1);
    o.z = warp_one(img, fh.z, fw.z, h, w + 2);
    o.w = warp_one(img, fh.w, fw.w, h, w + 3);

    *reinterpret_cast<float4*>(out + base) = o;
}

extern "C" void kernel_launch(void* const* d_in, const int* in_sizes, int n_in,
                              void* d_out, int out_size) {
    const float* img   = (const float*)d_in[0];                       // [1,1,H,W]
    const float* flowH = (const float*)d_in[1];                       // plane 0
    const float* flowW = (const float*)d_in[1] + (size_t)H_DIM * W_DIM; // plane 1
    float* out = (float*)d_out;

    const size_t n_pix = (size_t)H_DIM * W_DIM;
    const int threads = 256;
    const int blocks = (int)((n_pix / 4 + threads - 1) / threads);
    dense_warp_kernel<<<blocks, threads>>>(img, flowH, flowW, out);
}